// round 14
// baseline (speedup 1.0000x reference)
#include <cuda_runtime.h>
#include <stdint.h>

#define FULLMASK 0xffffffffu

// e4m3 encodings: +1 = 0x38, -1 = 0xB8, 0 = 0x00 (all exact)

// ---------------- scratch (device globals; referenced ONLY in device code) ----------------
// activations e4m3 (+1/-1) bytes, NHWC
__device__ __align__(256) uint8_t g_X2[128*32*32*128];
__device__ __align__(256) uint8_t g_X3[128*16*16*128];
__device__ __align__(256) uint8_t g_X4[128*16*16*256];
__device__ __align__(256) uint8_t g_X5[128*8*8*256];
__device__ __align__(256) uint8_t g_X6[128*8*8*512];
__device__ __align__(256) float   g_H6[128*4*4*512];
// weights e4m3 +-1, FRAGMENT-MAJOR blocks of 256B:
// block idx (((tap*(COUT/32)+nblk)*(CIN/32)+kc)*4+nf); within: lane*8 bytes =
// b0 (cout=nblk*32+nf*8+group, k=kc*32+tig*4..+3), b1 (k=kc*32+16+tig*4..+3)
__device__ __align__(256) uint8_t g_B2[9*128*128];
__device__ __align__(256) uint8_t g_B3[9*256*128];
__device__ __align__(256) uint8_t g_B4[9*256*256];
__device__ __align__(256) uint8_t g_B5[9*512*256];
__device__ __align__(256) uint8_t g_B6[9*512*512];

// ---------------- weight sign-packing to e4m3 (fragment-major) ----------------
// one thread per 8-byte lane slot
__device__ __forceinline__ void pack8(const float* __restrict__ w, uint8_t* __restrict__ bt,
                                      int CIN, int COUT, int o)
{
    int lane = o & 31;
    int nf   = (o >> 5) & 3;
    int rest = o >> 7;
    int KCL  = CIN / 32;
    int kc   = rest % KCL;
    int r2   = rest / KCL;
    int nblk = r2 % (COUT / 32);
    int tap  = r2 / (COUT / 32);
    int group = lane >> 2, tig = lane & 3;
    int cout = nblk * 32 + nf * 8 + group;
    uint32_t wd[2];
    #pragma unroll
    for (int half = 0; half < 2; ++half) {
        uint32_t v = 0;
        #pragma unroll
        for (int j = 0; j < 4; ++j) {
            int k = kc * 32 + half * 16 + tig * 4 + j;
            uint32_t bb = (w[((size_t)tap * CIN + k) * COUT + cout] > 0.f) ? 0x38u : 0xB8u;
            v |= bb << (8 * j);
        }
        wd[half] = v;
    }
    *reinterpret_cast<uint2*>(bt + (size_t)o * 8) = make_uint2(wd[0], wd[1]);
}

__global__ void pack_all(const float* __restrict__ w2, const float* __restrict__ w3,
                         const float* __restrict__ w4, const float* __restrict__ w5,
                         const float* __restrict__ w6)
{
    int idx = blockIdx.x * blockDim.x + threadIdx.x;
    if      (idx <  18432) pack8(w2, g_B2, 128, 128, idx);
    else if (idx <  55296) pack8(w3, g_B3, 128, 256, idx - 18432);
    else if (idx < 129024) pack8(w4, g_B4, 256, 256, idx - 55296);
    else if (idx < 276480) pack8(w5, g_B5, 256, 512, idx - 129024);
    else if (idx < 571392) pack8(w6, g_B6, 512, 512, idx - 276480);
}

// ---------------- layer 1: float conv 3->128 + relu + b1 + bn1 -> e4m3 sign ----------------
__global__ __launch_bounds__(128) void conv1_kernel(
    const float* __restrict__ x, const float* __restrict__ w1,
    const float* __restrict__ b1, const float* __restrict__ sc1,
    const float* __restrict__ bi1)
{
    __shared__ float xs[3 * 34 * 3];
    const int tid = threadIdx.x;
    const int y = blockIdx.x, b = blockIdx.y;

    for (int i = tid; i < 3 * 34 * 3; i += 128) xs[i] = 0.f;
    __syncthreads();
    for (int j = 0; j < 3; ++j) {
        int gy = y + j - 1;
        if (gy < 0 || gy >= 32) continue;
        if (tid < 96) {
            int c = tid / 3, ci = tid % 3;
            xs[(j * 34 + c + 1) * 3 + ci] = x[((size_t)(b * 32 + gy) * 32 + c) * 3 + ci];
        }
    }
    __syncthreads();

    float wr[27];
    #pragma unroll
    for (int k = 0; k < 27; ++k) wr[k] = w1[k * 128 + tid];
    const float bv = b1[tid], scv = sc1[tid], biv = bi1[tid];

    for (int c = 0; c < 32; ++c) {
        float sum = 0.f;
        #pragma unroll
        for (int ky = 0; ky < 3; ++ky)
            #pragma unroll
            for (int kx = 0; kx < 3; ++kx)
                #pragma unroll
                for (int ci = 0; ci < 3; ++ci)
                    sum += xs[(ky * 34 + c + kx) * 3 + ci] * wr[(ky * 3 + kx) * 3 + ci];
        float h = fmaxf(sum + bv, 0.f);
        float f = __fadd_rn(__fmul_rn(h, scv), biv);
        g_X2[((size_t)(b * 32 + y) * 32 + c) * 128 + tid] = (f > 0.f) ? 0x38 : 0xB8;
    }
}

// ---------------- layer params (CTA tile M=64 x N=128; warp tile m64 x n32) ----------------
template <int L> struct LP;
template <> struct LP<2> { static constexpr int H=32,W=32,CIN=128,COUT=128; static constexpr bool POOL=true,  FOUT=false; };
template <> struct LP<3> { static constexpr int H=16,W=16,CIN=128,COUT=256; static constexpr bool POOL=false, FOUT=false; };
template <> struct LP<4> { static constexpr int H=16,W=16,CIN=256,COUT=256; static constexpr bool POOL=true,  FOUT=false; };
template <> struct LP<5> { static constexpr int H=8, W=8, CIN=256,COUT=512; static constexpr bool POOL=false, FOUT=false; };
template <> struct LP<6> { static constexpr int H=8, W=8, CIN=512,COUT=512; static constexpr bool POOL=true,  FOUT=true;  };

// ---------------- binary conv: e4m3 mma implicit GEMM ----------------
// block 128 thr = 4 n-warps; warp tile m64 x n32 (4 mi x 4 nf), k32 e4m3 mma.
template <int L>
__global__ __launch_bounds__(128) void tcconv(const float* __restrict__ scale,
                                              const float* __restrict__ bias)
{
    constexpr int H = LP<L>::H, W = LP<L>::W, CIN = LP<L>::CIN, COUT = LP<L>::COUT;
    constexpr bool POOL = LP<L>::POOL, FOUT = LP<L>::FOUT;
    constexpr int MROWS = 64 / W;
    constexpr int TPI = H / MROWS;
    constexpr int SROWS = MROWS + 2;
    constexpr int CPP = CIN / 16;                   // 16B units per pixel
    constexpr int KC = CIN / 32;                    // k32 chunks per tap
    constexpr int A_BYTES = SROWS * W * CIN;
    constexpr int RES_BYTES = 64 * 132 * 4;
    constexpr int SM_BYTES = (A_BYTES > RES_BYTES ? A_BYTES : RES_BYTES);

    const uint8_t* __restrict__ Xin;
    const uint8_t* __restrict__ BT;
    uint8_t* __restrict__ Xout = nullptr;
    float*   __restrict__ Fout = nullptr;
    if constexpr (L == 2)      { Xin = g_X2; BT = g_B2; Xout = g_X3; }
    else if constexpr (L == 3) { Xin = g_X3; BT = g_B3; Xout = g_X4; }
    else if constexpr (L == 4) { Xin = g_X4; BT = g_B4; Xout = g_X5; }
    else if constexpr (L == 5) { Xin = g_X5; BT = g_B5; Xout = g_X6; }
    else                       { Xin = g_X6; BT = g_B6; Fout = g_H6; }

    __shared__ __align__(16) uint8_t smem[SM_BYTES + 16];
    float* sR = reinterpret_cast<float*>(smem);

    const int tid  = threadIdx.x;
    const int lane = tid & 31, wn = tid >> 5;       // 4 n-warps
    const int group = lane >> 2, tig = lane & 3;
    const int q = lane >> 3, rr = lane & 7;
    const int h = q >> 1;                           // k16-half (16B unit) this lane feeds

    const int bx = blockIdx.x, ny = blockIdx.y;
    const int b = bx / TPI, tile = bx % TPI;
    const int iy0 = tile * MROWS;
    const int nybase = ny * 128;
    const int nb = ny * 4 + wn;                     // global 32-cout block for this warp

    const uint32_t sbase = (uint32_t)__cvta_generic_to_shared(smem);
    const uint32_t zaddr = sbase + SM_BYTES;
    if (tid < 4) *reinterpret_cast<uint32_t*>(smem + SM_BYTES + tid * 4) = 0u;

    // per-lane A pixel per m-frag (4 frags -> m64)
    int ry[4], px[4];
    #pragma unroll
    for (int mi = 0; mi < 4; ++mi) {
        int p = mi * 16 + (q & 1) * 8 + rr;
        ry[mi] = p / W; px[mi] = p - ry[mi] * W;
    }

    // ---- stage A rows iy0-1 .. iy0+MROWS, pixel-XOR swizzled (16B units) ----
    {
        constexpr int NV = SROWS * W * CPP;
        for (int i = tid; i < NV; i += 128) {
            int sp = i / CPP, c16 = i - sp * CPP;
            int gy = iy0 - 1 + sp / W, gx = sp % W;
            uint4 v = make_uint4(0, 0, 0, 0);
            if ((unsigned)gy < (unsigned)H)
                v = *reinterpret_cast<const uint4*>(
                    Xin + (((size_t)b * H + gy) * W + gx) * CIN + c16 * 16);
            int d16 = sp * CPP + (c16 ^ (sp & 7));
            *reinterpret_cast<uint4*>(smem + d16 * 16) = v;
        }
    }
    __syncthreads();

    float acc[4][4][4];
    #pragma unroll
    for (int mi = 0; mi < 4; ++mi)
        #pragma unroll
        for (int nf = 0; nf < 4; ++nf)
            #pragma unroll
            for (int v = 0; v < 4; ++v) acc[mi][nf][v] = 0.f;

    for (int tap = 0; tap < 9; ++tap) {
        const int ky = tap / 3, kx = tap % 3;
        uint32_t abase[4], ax7[4]; bool av[4];
        #pragma unroll
        for (int mi = 0; mi < 4; ++mi) {
            int sx = px[mi] + kx - 1;
            av[mi] = ((unsigned)sx < (unsigned)W);         // row halo staged as zeros
            int sp = (ry[mi] + ky) * W + sx;
            abase[mi] = sbase + (uint32_t)(sp * CPP * 16);
            ax7[mi]   = (uint32_t)(sp & 7);
        }
        // fragment-major B: this warp's 256B fragment rows
        const uint2* Bw = reinterpret_cast<const uint2*>(BT)
            + (((size_t)tap * (COUT / 32) + nb) * KC) * 128 + lane;
        #pragma unroll 2
        for (int kc = 0; kc < KC; ++kc) {
            uint32_t A[4][4];
            #pragma unroll
            for (int mi = 0; mi < 4; ++mi) {
                uint32_t u = ((uint32_t)(kc * 2 + h)) ^ ax7[mi];
                uint32_t ad = av[mi] ? (abase[mi] + (u << 4)) : zaddr;
                asm volatile(
                    "ldmatrix.sync.aligned.m8n8.x4.shared.b16 {%0,%1,%2,%3}, [%4];"
                    : "=r"(A[mi][0]), "=r"(A[mi][1]), "=r"(A[mi][2]), "=r"(A[mi][3])
                    : "r"(ad));
            }
            #pragma unroll
            for (int nf = 0; nf < 4; ++nf) {
                uint2 bw = Bw[(kc * 4 + nf) * 32];
                #pragma unroll
                for (int mi = 0; mi < 4; ++mi) {
                    asm volatile(
                        "mma.sync.aligned.m16n8k32.row.col.f32.e4m3.e4m3.f32 "
                        "{%0,%1,%2,%3}, {%4,%5,%6,%7}, {%8,%9}, {%0,%1,%2,%3};"
                        : "+f"(acc[mi][nf][0]), "+f"(acc[mi][nf][1]),
                          "+f"(acc[mi][nf][2]), "+f"(acc[mi][nf][3])
                        : "r"(A[mi][0]), "r"(A[mi][1]), "r"(A[mi][2]), "r"(A[mi][3]),
                          "r"(bw.x), "r"(bw.y));
                }
            }
        }
    }
    __syncthreads();   // A no longer needed; reuse smem for results

    // spill accumulators: sR[pixel][n], pitch 132
    #pragma unroll
    for (int mi = 0; mi < 4; ++mi) {
        int r0 = mi * 16 + group;
        #pragma unroll
        for (int nf = 0; nf < 4; ++nf) {
            int col = wn * 32 + nf * 8 + tig * 2;
            *reinterpret_cast<float2*>(&sR[r0 * 132 + col]) =
                make_float2(acc[mi][nf][0], acc[mi][nf][1]);
            *reinterpret_cast<float2*>(&sR[(r0 + 8) * 132 + col]) =
                make_float2(acc[mi][nf][2], acc[mi][nf][3]);
        }
    }
    __syncthreads();

    // ---- epilogue: relu (+pool) + bn + sign/float store ----
    if constexpr (POOL) {
        // 16 out px x 128 n; 8 threads per px, 16 n each
        int po = tid >> 3;
        int n0 = (tid & 7) * 16;
        int yo_l = po / (W / 2), xo_l = po % (W / 2);
        int p00 = (2 * yo_l) * W + 2 * xo_l;
        float fv[16];
        #pragma unroll
        for (int j = 0; j < 16; ++j) {
            int n = n0 + j;
            float m = fmaxf(fmaxf(sR[p00 * 132 + n],       sR[(p00 + 1) * 132 + n]),
                            fmaxf(sR[(p00 + W) * 132 + n], sR[(p00 + W + 1) * 132 + n]));
            m = fmaxf(m, 0.f);
            int ng = nybase + n;
            fv[j] = __fadd_rn(__fmul_rn(m, scale[ng]), bias[ng]);
        }
        int yo = iy0 / 2 + yo_l;
        size_t obase = (((size_t)b * (H / 2) + yo) * (W / 2) + xo_l) * COUT + nybase + n0;
        if constexpr (FOUT) {
            #pragma unroll
            for (int qq = 0; qq < 4; ++qq)
                *reinterpret_cast<float4*>(Fout + obase + qq * 4) =
                    make_float4(fv[4*qq], fv[4*qq+1], fv[4*qq+2], fv[4*qq+3]);
        } else {
            uint32_t wds[4];
            #pragma unroll
            for (int qq = 0; qq < 4; ++qq) {
                uint32_t v = 0;
                #pragma unroll
                for (int j = 0; j < 4; ++j)
                    v |= ((fv[4*qq + j] > 0.f) ? 0x38u : 0xB8u) << (8 * j);
                wds[qq] = v;
            }
            *reinterpret_cast<uint4*>(Xout + obase) = make_uint4(wds[0], wds[1], wds[2], wds[3]);
        }
    } else {
        // 64 px x 128 n; 8 iterations of 128 thr x 8 n
        #pragma unroll
        for (int it = 0; it < 8; ++it) {
            int t = it * 128 + tid;
            int lp = t >> 4;
            int n0 = (t & 15) * 8;
            int y = iy0 + lp / W, x = lp % W;
            uint32_t wds[2];
            #pragma unroll
            for (int qq = 0; qq < 2; ++qq) {
                uint32_t v = 0;
                #pragma unroll
                for (int j = 0; j < 4; ++j) {
                    int n = n0 + qq * 4 + j;
                    float vv = fmaxf(sR[lp * 132 + n], 0.f);
                    int ng = nybase + n;
                    float f = __fadd_rn(__fmul_rn(vv, scale[ng]), bias[ng]);
                    v |= ((f > 0.f) ? 0x38u : 0xB8u) << (8 * j);
                }
                wds[qq] = v;
            }
            size_t obase = (((size_t)b * H + y) * W + x) * COUT + nybase + n0;
            *reinterpret_cast<uint2*>(Xout + obase) = make_uint2(wds[0], wds[1]);
        }
    }
}

// ---------------- dense (512->10) + softmax, one warp per pixel ----------------
__global__ __launch_bounds__(128) void dense_kernel(
    const float* __restrict__ dw, const float* __restrict__ db, float* __restrict__ out)
{
    __shared__ float sdw[512 * 10];
    const int tid = threadIdx.x;
    for (int i = tid; i < 5120; i += 128) {
        int c = i / 10, d = i % 10;
        sdw[d * 512 + c] = dw[i];
    }
    __syncthreads();
    const int warp = tid >> 5, lane = tid & 31;
    const int p = blockIdx.x * 4 + warp;
    float lg[10];
    #pragma unroll
    for (int d = 0; d < 10; ++d) lg[d] = 0.f;
    for (int c = lane; c < 512; c += 32) {
        float hh = g_H6[(size_t)p * 512 + c];
        #pragma unroll
        for (int d = 0; d < 10; ++d) lg[d] += hh * sdw[d * 512 + c];
    }
    #pragma unroll
    for (int d = 0; d < 10; ++d)
        for (int off = 16; off; off >>= 1)
            lg[d] += __shfl_xor_sync(FULLMASK, lg[d], off);
    if (lane == 0) {
        float l[10], mx = -1e30f;
        #pragma unroll
        for (int d = 0; d < 10; ++d) { l[d] = lg[d] + db[d]; mx = fmaxf(mx, l[d]); }
        float e[10], ssum = 0.f;
        #pragma unroll
        for (int d = 0; d < 10; ++d) { e[d] = expf(l[d] - mx); ssum += e[d]; }
        float inv = 1.f / ssum;
        #pragma unroll
        for (int d = 0; d < 10; ++d) out[(size_t)p * 10 + d] = e[d] * inv;
    }
}

// ---------------- launch ----------------
extern "C" void kernel_launch(void* const* d_in, const int* in_sizes, int n_in,
                              void* d_out, int out_size)
{
    const float* P[22];
    for (int i = 0; i < 22 && i < n_in; ++i) P[i] = (const float*)d_in[i];

    const float *x, *w1, *b1, *w2, *w3, *w4, *w5, *w6;
    const float *bn1s, *bn1b, *bn2s, *bn2b, *bn3s, *bn3b, *bn4s, *bn4b, *bn5s, *bn5b, *bn6s, *bn6b;
    const float *dw, *db;

    if (in_sizes[3] == 147456) {
        // setup_inputs dict order
        x = P[0];  w1 = P[1]; b1 = P[2];
        w2 = P[3]; w3 = P[4]; w4 = P[5]; w5 = P[6]; w6 = P[7];
        bn1s = P[8];  bn1b = P[9];  bn2s = P[10]; bn2b = P[11];
        bn3s = P[12]; bn3b = P[13]; bn4s = P[14]; bn4b = P[15];
        bn5s = P[16]; bn5b = P[17]; bn6s = P[18]; bn6b = P[19];
        dw = P[20]; db = P[21];
    } else {
        // reference() signature order
        x = P[0];  w1 = P[1]; b1 = P[2]; bn1s = P[3]; bn1b = P[4];
        w2 = P[5];  bn2s = P[6];  bn2b = P[7];
        w3 = P[8];  bn3s = P[9];  bn3b = P[10];
        w4 = P[11]; bn4s = P[12]; bn4b = P[13];
        w5 = P[14]; bn5s = P[15]; bn5b = P[16];
        w6 = P[17]; bn6s = P[18]; bn6b = P[19];
        dw = P[20]; db = P[21];
    }

    pack_all<<<(571392 + 255) / 256, 256>>>(w2, w3, w4, w5, w6);

    conv1_kernel<<<dim3(32, 128), 128>>>(x, w1, b1, bn1s, bn1b);

    tcconv<2><<<dim3(128 * 16, 1), 128>>>(bn2s, bn2b);
    tcconv<3><<<dim3(128 * 4, 2),  128>>>(bn3s, bn3b);
    tcconv<4><<<dim3(128 * 4, 2),  128>>>(bn4s, bn4b);
    tcconv<5><<<dim3(128, 4),      128>>>(bn5s, bn5b);
    tcconv<6><<<dim3(128, 4),      128>>>(bn6s, bn6b);

    dense_kernel<<<512, 128>>>(dw, db, (float*)d_out);
}

// round 15
// speedup vs baseline: 1.1670x; 1.1670x over previous
#include <cuda_runtime.h>
#include <stdint.h>

#define FULLMASK 0xffffffffu

// ---------------- scratch (device globals; referenced ONLY in device code) ----------------
// activations bf16 (+1/-1) raw uint16, NHWC
__device__ __align__(256) uint16_t g_X2[128*32*32*128];
__device__ __align__(256) uint16_t g_X3[128*16*16*128];
__device__ __align__(256) uint16_t g_X4[128*16*16*256];
__device__ __align__(256) uint16_t g_X5[128*8*8*256];
__device__ __align__(256) uint16_t g_X6[128*8*8*512];
__device__ __align__(256) float    g_H6[128*4*4*512];
// weights bf16 +-1, FRAGMENT-MAJOR: 8B block for (tap, nblk, kcf, nf, lane) at
// linear block idx (((tap*(COUT/32)+nblk)*(CIN/16)+kcf)*4+nf)*32+lane, so a
// warp's B fragment load is one contiguous 256B LDG.64.  (validated R12)
__device__ __align__(256) uint16_t g_B2[9*128*128];
__device__ __align__(256) uint16_t g_B3[9*256*128];
__device__ __align__(256) uint16_t g_B4[9*256*256];
__device__ __align__(256) uint16_t g_B5[9*512*256];
__device__ __align__(256) uint16_t g_B6[9*512*512];

// ---------------- weight sign-packing to bf16 +-1 (fragment-major, validated R12) ----------------
__device__ __forceinline__ void pack16(const float* __restrict__ w, uint16_t* __restrict__ bt,
                                       int CIN, int COUT, int o)
{
    int cout = o % COUT;
    int r    = o / COUT;
    int kcf  = r % (CIN / 16);
    int tap  = r / (CIN / 16);
    const float* base = w + ((size_t)(tap * CIN + kcf * 16)) * COUT + cout;
    uint32_t wd[8];
    #pragma unroll
    for (int qq = 0; qq < 8; ++qq) {
        int k0 = (qq & 1) * 8 + (qq >> 1) * 2;
        uint32_t lo = (base[(size_t)k0 * COUT]       > 0.f) ? 0x3F80u : 0xBF80u;
        uint32_t hi = (base[(size_t)(k0 + 1) * COUT] > 0.f) ? 0x3F80u : 0xBF80u;
        wd[qq] = lo | (hi << 16);
    }
    int nblk = cout >> 5;
    int nf   = (cout >> 3) & 3;
    int group = cout & 7;
    size_t blk8 = ((((size_t)tap * (COUT / 32) + nblk) * (CIN / 16) + kcf) * 4 + nf) * 32
                  + group * 4;     // tig 0..3 occupy 4 consecutive 8B slots
    uint4* dst = reinterpret_cast<uint4*>(bt + blk8 * 4);
    dst[0] = make_uint4(wd[0], wd[1], wd[2], wd[3]);
    dst[1] = make_uint4(wd[4], wd[5], wd[6], wd[7]);
}

__global__ void pack_all(const float* __restrict__ w2, const float* __restrict__ w3,
                         const float* __restrict__ w4, const float* __restrict__ w5,
                         const float* __restrict__ w6)
{
    int idx = blockIdx.x * blockDim.x + threadIdx.x;
    if      (idx <   9216) pack16(w2, g_B2, 128, 128, idx);
    else if (idx <  27648) pack16(w3, g_B3, 128, 256, idx - 9216);
    else if (idx <  64512) pack16(w4, g_B4, 256, 256, idx - 27648);
    else if (idx < 138240) pack16(w5, g_B5, 256, 512, idx - 64512);
    else if (idx < 285696) pack16(w6, g_B6, 512, 512, idx - 138240);
}

// ---------------- layer 1: float conv 3->128 + relu + b1 + bn1 -> bf16 sign ----------------
__global__ __launch_bounds__(128) void conv1_kernel(
    const float* __restrict__ x, const float* __restrict__ w1,
    const float* __restrict__ b1, const float* __restrict__ sc1,
    const float* __restrict__ bi1)
{
    __shared__ float xs[3 * 34 * 3];
    const int tid = threadIdx.x;
    const int y = blockIdx.x, b = blockIdx.y;

    for (int i = tid; i < 3 * 34 * 3; i += 128) xs[i] = 0.f;
    __syncthreads();
    for (int j = 0; j < 3; ++j) {
        int gy = y + j - 1;
        if (gy < 0 || gy >= 32) continue;
        if (tid < 96) {
            int c = tid / 3, ci = tid % 3;
            xs[(j * 34 + c + 1) * 3 + ci] = x[((size_t)(b * 32 + gy) * 32 + c) * 3 + ci];
        }
    }
    __syncthreads();

    float wr[27];
    #pragma unroll
    for (int k = 0; k < 27; ++k) wr[k] = w1[k * 128 + tid];
    const float bv = b1[tid], scv = sc1[tid], biv = bi1[tid];

    for (int c = 0; c < 32; ++c) {
        float sum = 0.f;
        #pragma unroll
        for (int ky = 0; ky < 3; ++ky)
            #pragma unroll
            for (int kx = 0; kx < 3; ++kx)
                #pragma unroll
                for (int ci = 0; ci < 3; ++ci)
                    sum += xs[(ky * 34 + c + kx) * 3 + ci] * wr[(ky * 3 + kx) * 3 + ci];
        float h = fmaxf(sum + bv, 0.f);
        float f = __fadd_rn(__fmul_rn(h, scv), biv);
        g_X2[((size_t)(b * 32 + y) * 32 + c) * 128 + tid] = (f > 0.f) ? 0x3F80 : 0xBF80;
    }
}

// ---------------- layer params (CTA tile M=64 x N=128; warp tile m64 x n32) ----------------
template <int L> struct LP;
template <> struct LP<2> { static constexpr int H=32,W=32,CIN=128,COUT=128,KSPLIT=1; static constexpr bool POOL=true,  FOUT=false; };
template <> struct LP<3> { static constexpr int H=16,W=16,CIN=128,COUT=256,KSPLIT=1; static constexpr bool POOL=false, FOUT=false; };
template <> struct LP<4> { static constexpr int H=16,W=16,CIN=256,COUT=256,KSPLIT=2; static constexpr bool POOL=true,  FOUT=false; };
template <> struct LP<5> { static constexpr int H=8, W=8, CIN=256,COUT=512,KSPLIT=1; static constexpr bool POOL=false, FOUT=false; };
template <> struct LP<6> { static constexpr int H=8, W=8, CIN=512,COUT=512,KSPLIT=2; static constexpr bool POOL=true,  FOUT=true;  };

// ---------------- binary conv: bf16 HMMA implicit GEMM, pipelined mainloop ----------------
// block 128 thr = 4 n-warps; warp tile m64 x n32 (4 mi x 4 nf), k16 bf16 mma.
template <int L>
__global__ __launch_bounds__(128) void tcconv(const float* __restrict__ scale,
                                              const float* __restrict__ bias)
{
    constexpr int H = LP<L>::H, W = LP<L>::W, CIN = LP<L>::CIN, COUT = LP<L>::COUT;
    constexpr int KSPLIT = LP<L>::KSPLIT;
    constexpr bool POOL = LP<L>::POOL, FOUT = LP<L>::FOUT;
    constexpr int MROWS = 64 / W;
    constexpr int TPI = H / MROWS;
    constexpr int SROWS = MROWS + 2;
    constexpr int CINS = CIN / KSPLIT;
    constexpr int CPP16 = CINS / 8;                 // 16B units per pixel (per ks chunk)
    constexpr int KC = CINS / 16;                   // k16 chunks per tap per ks
    constexpr int A_BYTES = SROWS * W * CINS * 2;
    constexpr int RES_BYTES = 64 * 132 * 4;
    constexpr int SM_BYTES = (A_BYTES > RES_BYTES ? A_BYTES : RES_BYTES);

    const uint16_t* __restrict__ Xin;
    const uint16_t* __restrict__ BT;
    uint16_t* __restrict__ Xout = nullptr;
    float*    __restrict__ Fout = nullptr;
    if constexpr (L == 2)      { Xin = g_X2; BT = g_B2; Xout = g_X3; }
    else if constexpr (L == 3) { Xin = g_X3; BT = g_B3; Xout = g_X4; }
    else if constexpr (L == 4) { Xin = g_X4; BT = g_B4; Xout = g_X5; }
    else if constexpr (L == 5) { Xin = g_X5; BT = g_B5; Xout = g_X6; }
    else                       { Xin = g_X6; BT = g_B6; Fout = g_H6; }

    __shared__ __align__(16) uint8_t smem[SM_BYTES + 16];
    float* sR = reinterpret_cast<float*>(smem);

    const int tid  = threadIdx.x;
    const int lane = tid & 31, wn = tid >> 5;       // 4 n-warps
    const int group = lane >> 2, tig = lane & 3;
    const int q = lane >> 3, rr = lane & 7;
    const int h = q >> 1;                           // k16-half (16B unit) this lane feeds

    const int bx = blockIdx.x, ny = blockIdx.y;
    const int b = bx / TPI, tile = bx % TPI;
    const int iy0 = tile * MROWS;
    const int nybase = ny * 128;
    const int nb = ny * 4 + wn;                     // global 32-cout block for this warp

    const uint32_t sbase = (uint32_t)__cvta_generic_to_shared(smem);
    const uint32_t zaddr = sbase + SM_BYTES;
    if (tid < 4) *reinterpret_cast<uint32_t*>(smem + SM_BYTES + tid * 4) = 0u;

    // per-lane A pixel per m-frag (4 frags -> m64)
    int ry[4], px[4];
    #pragma unroll
    for (int mi = 0; mi < 4; ++mi) {
        int p = mi * 16 + (q & 1) * 8 + rr;
        ry[mi] = p / W; px[mi] = p - ry[mi] * W;
    }

    float acc[4][4][4];
    #pragma unroll
    for (int mi = 0; mi < 4; ++mi)
        #pragma unroll
        for (int nf = 0; nf < 4; ++nf)
            #pragma unroll
            for (int v = 0; v < 4; ++v) acc[mi][nf][v] = 0.f;

    for (int ks = 0; ks < KSPLIT; ++ks) {
        if (ks) __syncthreads();
        // ---- stage A rows iy0-1 .. iy0+MROWS of k-chunk ks, pixel-XOR swizzled ----
        {
            constexpr int NV = SROWS * W * CPP16;
            for (int i = tid; i < NV; i += 128) {
                int sp = i / CPP16, c16 = i - sp * CPP16;
                int gy = iy0 - 1 + sp / W, gx = sp % W;
                uint4 v = make_uint4(0, 0, 0, 0);
                if ((unsigned)gy < (unsigned)H)
                    v = *reinterpret_cast<const uint4*>(
                        Xin + (((size_t)b * H + gy) * W + gx) * CIN + ks * CINS + c16 * 8);
                int d16 = sp * CPP16 + (c16 ^ (sp & 7));
                *reinterpret_cast<uint4*>(smem + d16 * 16) = v;
            }
        }
        __syncthreads();

        for (int tap = 0; tap < 9; ++tap) {
            const int ky = tap / 3, kx = tap % 3;
            uint32_t abase[4], ax7[4]; bool av[4];
            #pragma unroll
            for (int mi = 0; mi < 4; ++mi) {
                int sx = px[mi] + kx - 1;
                av[mi] = ((unsigned)sx < (unsigned)W);     // row halo staged as zeros
                int sp = (ry[mi] + ky) * W + sx;
                abase[mi] = sbase + (uint32_t)(sp * CPP16 * 16);
                ax7[mi]   = (uint32_t)(sp & 7);
            }
            // fragment-major B: warp's fragment row = 128 uint2 per kcf
            const uint2* Bw = reinterpret_cast<const uint2*>(BT)
                + (((size_t)tap * (COUT / 32) + nb) * (CIN / 16) + ks * KC) * 128 + lane;

            // ---- software-pipelined kc loop (depth-1 prefetch, fully unrolled) ----
            uint32_t Ac[4][4];
            uint2 Bc[4];
            #pragma unroll
            for (int mi = 0; mi < 4; ++mi) {
                uint32_t u = ((uint32_t)h) ^ ax7[mi];
                uint32_t ad = av[mi] ? (abase[mi] + (u << 4)) : zaddr;
                asm volatile(
                    "ldmatrix.sync.aligned.m8n8.x4.shared.b16 {%0,%1,%2,%3}, [%4];"
                    : "=r"(Ac[mi][0]), "=r"(Ac[mi][1]), "=r"(Ac[mi][2]), "=r"(Ac[mi][3])
                    : "r"(ad));
            }
            #pragma unroll
            for (int nf = 0; nf < 4; ++nf) Bc[nf] = Bw[nf * 32];

            #pragma unroll
            for (int kc = 0; kc < KC; ++kc) {
                uint32_t An[4][4];
                uint2 Bn[4];
                if (kc + 1 < KC) {
                    #pragma unroll
                    for (int mi = 0; mi < 4; ++mi) {
                        uint32_t u = ((uint32_t)((kc + 1) * 2 + h)) ^ ax7[mi];
                        uint32_t ad = av[mi] ? (abase[mi] + (u << 4)) : zaddr;
                        asm volatile(
                            "ldmatrix.sync.aligned.m8n8.x4.shared.b16 {%0,%1,%2,%3}, [%4];"
                            : "=r"(An[mi][0]), "=r"(An[mi][1]), "=r"(An[mi][2]), "=r"(An[mi][3])
                            : "r"(ad));
                    }
                    #pragma unroll
                    for (int nf = 0; nf < 4; ++nf) Bn[nf] = Bw[((kc + 1) * 4 + nf) * 32];
                }
                #pragma unroll
                for (int nf = 0; nf < 4; ++nf) {
                    #pragma unroll
                    for (int mi = 0; mi < 4; ++mi) {
                        asm volatile(
                            "mma.sync.aligned.m16n8k16.row.col.f32.bf16.bf16.f32 "
                            "{%0,%1,%2,%3}, {%4,%5,%6,%7}, {%8,%9}, {%0,%1,%2,%3};"
                            : "+f"(acc[mi][nf][0]), "+f"(acc[mi][nf][1]),
                              "+f"(acc[mi][nf][2]), "+f"(acc[mi][nf][3])
                            : "r"(Ac[mi][0]), "r"(Ac[mi][1]), "r"(Ac[mi][2]), "r"(Ac[mi][3]),
                              "r"(Bc[nf].x), "r"(Bc[nf].y));
                    }
                }
                if (kc + 1 < KC) {
                    #pragma unroll
                    for (int mi = 0; mi < 4; ++mi)
                        #pragma unroll
                        for (int j = 0; j < 4; ++j) Ac[mi][j] = An[mi][j];
                    #pragma unroll
                    for (int nf = 0; nf < 4; ++nf) Bc[nf] = Bn[nf];
                }
            }
        }
    }
    __syncthreads();   // A no longer needed; reuse smem for results

    // spill accumulators: sR[pixel][n], pitch 132
    #pragma unroll
    for (int mi = 0; mi < 4; ++mi) {
        int r0 = mi * 16 + group;
        #pragma unroll
        for (int nf = 0; nf < 4; ++nf) {
            int col = wn * 32 + nf * 8 + tig * 2;
            *reinterpret_cast<float2*>(&sR[r0 * 132 + col]) =
                make_float2(acc[mi][nf][0], acc[mi][nf][1]);
            *reinterpret_cast<float2*>(&sR[(r0 + 8) * 132 + col]) =
                make_float2(acc[mi][nf][2], acc[mi][nf][3]);
        }
    }
    __syncthreads();

    // ---- epilogue: relu (+pool) + bn + sign/float store ----
    if constexpr (POOL) {
        // 16 out px x 128 n; 8 threads per px, 16 n each
        int po = tid >> 3;
        int n0 = (tid & 7) * 16;
        int yo_l = po / (W / 2), xo_l = po % (W / 2);
        int p00 = (2 * yo_l) * W + 2 * xo_l;
        float fv[16];
        #pragma unroll
        for (int j = 0; j < 16; ++j) {
            int n = n0 + j;
            float m = fmaxf(fmaxf(sR[p00 * 132 + n],       sR[(p00 + 1) * 132 + n]),
                            fmaxf(sR[(p00 + W) * 132 + n], sR[(p00 + W + 1) * 132 + n]));
            m = fmaxf(m, 0.f);
            int ng = nybase + n;
            fv[j] = __fadd_rn(__fmul_rn(m, scale[ng]), bias[ng]);
        }
        int yo = iy0 / 2 + yo_l;
        size_t obase = (((size_t)b * (H / 2) + yo) * (W / 2) + xo_l) * COUT + nybase + n0;
        if constexpr (FOUT) {
            #pragma unroll
            for (int qq = 0; qq < 4; ++qq)
                *reinterpret_cast<float4*>(Fout + obase + qq * 4) =
                    make_float4(fv[4*qq], fv[4*qq+1], fv[4*qq+2], fv[4*qq+3]);
        } else {
            uint32_t wds[8];
            #pragma unroll
            for (int qq = 0; qq < 8; ++qq)
                wds[qq] = ((fv[2*qq]   > 0.f) ? 0x3F80u : 0xBF80u) |
                         (((fv[2*qq+1] > 0.f) ? 0x3F80u : 0xBF80u) << 16);
            uint4* op = reinterpret_cast<uint4*>(Xout + obase);
            op[0] = make_uint4(wds[0], wds[1], wds[2], wds[3]);
            op[1] = make_uint4(wds[4], wds[5], wds[6], wds[7]);
        }
    } else {
        // 64 px x 128 n; 8 iterations of 128 thr x 8 n
        #pragma unroll
        for (int it = 0; it < 8; ++it) {
            int t = it * 128 + tid;
            int lp = t >> 4;
            int n0 = (t & 15) * 8;
            int y = iy0 + lp / W, x = lp % W;
            float fv[8];
            #pragma unroll
            for (int j = 0; j < 8; ++j) {
                int n = n0 + j;
                float v = fmaxf(sR[lp * 132 + n], 0.f);
                int ng = nybase + n;
                fv[j] = __fadd_rn(__fmul_rn(v, scale[ng]), bias[ng]);
            }
            uint32_t wds[4];
            #pragma unroll
            for (int qq = 0; qq < 4; ++qq)
                wds[qq] = ((fv[2*qq]   > 0.f) ? 0x3F80u : 0xBF80u) |
                         (((fv[2*qq+1] > 0.f) ? 0x3F80u : 0xBF80u) << 16);
            size_t obase = (((size_t)b * H + y) * W + x) * COUT + nybase + n0;
            *reinterpret_cast<uint4*>(Xout + obase) = make_uint4(wds[0], wds[1], wds[2], wds[3]);
        }
    }
}

// ---------------- dense (512->10) + softmax, one warp per pixel ----------------
__global__ __launch_bounds__(128) void dense_kernel(
    const float* __restrict__ dw, const float* __restrict__ db, float* __restrict__ out)
{
    __shared__ float sdw[512 * 10];
    const int tid = threadIdx.x;
    for (int i = tid; i < 5120; i += 128) {
        int c = i / 10, d = i % 10;
        sdw[d * 512 + c] = dw[i];
    }
    __syncthreads();
    const int warp = tid >> 5, lane = tid & 31;
    const int p = blockIdx.x * 4 + warp;
    float lg[10];
    #pragma unroll
    for (int d = 0; d < 10; ++d) lg[d] = 0.f;
    for (int c = lane; c < 512; c += 32) {
        float hh = g_H6[(size_t)p * 512 + c];
        #pragma unroll
        for (int d = 0; d < 10; ++d) lg[d] += hh * sdw[d * 512 + c];
    }
    #pragma unroll
    for (int d = 0; d < 10; ++d)
        for (int off = 16; off; off >>= 1)
            lg[d] += __shfl_xor_sync(FULLMASK, lg[d], off);
    if (lane == 0) {
        float l[10], mx = -1e30f;
        #pragma unroll
        for (int d = 0; d < 10; ++d) { l[d] = lg[d] + db[d]; mx = fmaxf(mx, l[d]); }
        float e[10], ssum = 0.f;
        #pragma unroll
        for (int d = 0; d < 10; ++d) { e[d] = expf(l[d] - mx); ssum += e[d]; }
        float inv = 1.f / ssum;
        #pragma unroll
        for (int d = 0; d < 10; ++d) out[(size_t)p * 10 + d] = e[d] * inv;
    }
}

// ---------------- launch ----------------
extern "C" void kernel_launch(void* const* d_in, const int* in_sizes, int n_in,
                              void* d_out, int out_size)
{
    const float* P[22];
    for (int i = 0; i < 22 && i < n_in; ++i) P[i] = (const float*)d_in[i];

    const float *x, *w1, *b1, *w2, *w3, *w4, *w5, *w6;
    const float *bn1s, *bn1b, *bn2s, *bn2b, *bn3s, *bn3b, *bn4s, *bn4b, *bn5s, *bn5b, *bn6s, *bn6b;
    const float *dw, *db;

    if (in_sizes[3] == 147456) {
        // setup_inputs dict order
        x = P[0];  w1 = P[1]; b1 = P[2];
        w2 = P[3]; w3 = P[4]; w4 = P[5]; w5 = P[6]; w6 = P[7];
        bn1s = P[8];  bn1b = P[9];  bn2s = P[10]; bn2b = P[11];
        bn3s = P[12]; bn3b = P[13]; bn4s = P[14]; bn4b = P[15];
        bn5s = P[16]; bn5b = P[17]; bn6s = P[18]; bn6b = P[19];
        dw = P[20]; db = P[21];
    } else {
        // reference() signature order
        x = P[0];  w1 = P[1]; b1 = P[2]; bn1s = P[3]; bn1b = P[4];
        w2 = P[5];  bn2s = P[6];  bn2b = P[7];
        w3 = P[8];  bn3s = P[9];  bn3b = P[10];
        w4 = P[11]; bn4s = P[12]; bn4b = P[13];
        w5 = P[14]; bn5s = P[15]; bn5b = P[16];
        w6 = P[17]; bn6s = P[18]; bn6b = P[19];
        dw = P[20]; db = P[21];
    }

    pack_all<<<(285696 + 255) / 256, 256>>>(w2, w3, w4, w5, w6);

    conv1_kernel<<<dim3(32, 128), 128>>>(x, w1, b1, bn1s, bn1b);

    tcconv<2><<<dim3(128 * 16, 1), 128>>>(bn2s, bn2b);
    tcconv<3><<<dim3(128 * 4, 2),  128>>>(bn3s, bn3b);
    tcconv<4><<<dim3(128 * 4, 2),  128>>>(bn4s, bn4b);
    tcconv<5><<<dim3(128, 4),      128>>>(bn5s, bn5b);
    tcconv<6><<<dim3(128, 4),      128>>>(bn6s, bn6b);

    dense_kernel<<<512, 128>>>(dw, db, (float*)d_out);
}

// round 16
// speedup vs baseline: 1.1751x; 1.0069x over previous
#include <cuda_runtime.h>
#include <stdint.h>

#define FULLMASK 0xffffffffu

// ---------------- scratch (device globals; referenced ONLY in device code) ----------------
// activations bf16 (+1/-1) raw uint16, NHWC
__device__ __align__(256) uint16_t g_X2[128*32*32*128];
__device__ __align__(256) uint16_t g_X3[128*16*16*128];
__device__ __align__(256) uint16_t g_X4[128*16*16*256];
__device__ __align__(256) uint16_t g_X5[128*8*8*256];
__device__ __align__(256) uint16_t g_X6[128*8*8*512];
__device__ __align__(256) float    g_H6[128*4*4*512];
// weights bf16 +-1, FRAGMENT-MAJOR: 8B block for (tap, nblk, kcf, nf, lane) at
// linear block idx (((tap*(COUT/32)+nblk)*(CIN/16)+kcf)*4+nf)*32+lane, so a
// warp's B fragment load is one contiguous 256B LDG.64.  (validated R12)
__device__ __align__(256) uint16_t g_B2[9*128*128];
__device__ __align__(256) uint16_t g_B3[9*256*128];
__device__ __align__(256) uint16_t g_B4[9*256*256];
__device__ __align__(256) uint16_t g_B5[9*512*256];
__device__ __align__(256) uint16_t g_B6[9*512*512];

// ---------------- weight sign-packing to bf16 +-1 (fragment-major, validated R12) ----------------
__device__ __forceinline__ void pack16(const float* __restrict__ w, uint16_t* __restrict__ bt,
                                       int CIN, int COUT, int o)
{
    int cout = o % COUT;
    int r    = o / COUT;
    int kcf  = r % (CIN / 16);
    int tap  = r / (CIN / 16);
    const float* base = w + ((size_t)(tap * CIN + kcf * 16)) * COUT + cout;
    uint32_t wd[8];
    #pragma unroll
    for (int qq = 0; qq < 8; ++qq) {
        int k0 = (qq & 1) * 8 + (qq >> 1) * 2;
        uint32_t lo = (base[(size_t)k0 * COUT]       > 0.f) ? 0x3F80u : 0xBF80u;
        uint32_t hi = (base[(size_t)(k0 + 1) * COUT] > 0.f) ? 0x3F80u : 0xBF80u;
        wd[qq] = lo | (hi << 16);
    }
    int nblk = cout >> 5;
    int nf   = (cout >> 3) & 3;
    int group = cout & 7;
    size_t blk8 = ((((size_t)tap * (COUT / 32) + nblk) * (CIN / 16) + kcf) * 4 + nf) * 32
                  + group * 4;     // tig 0..3 occupy 4 consecutive 8B slots
    uint4* dst = reinterpret_cast<uint4*>(bt + blk8 * 4);
    dst[0] = make_uint4(wd[0], wd[1], wd[2], wd[3]);
    dst[1] = make_uint4(wd[4], wd[5], wd[6], wd[7]);
}

__global__ void pack_all(const float* __restrict__ w2, const float* __restrict__ w3,
                         const float* __restrict__ w4, const float* __restrict__ w5,
                         const float* __restrict__ w6)
{
    int idx = blockIdx.x * blockDim.x + threadIdx.x;
    if      (idx <   9216) pack16(w2, g_B2, 128, 128, idx);
    else if (idx <  27648) pack16(w3, g_B3, 128, 256, idx - 9216);
    else if (idx <  64512) pack16(w4, g_B4, 256, 256, idx - 27648);
    else if (idx < 138240) pack16(w5, g_B5, 256, 512, idx - 64512);
    else if (idx < 285696) pack16(w6, g_B6, 512, 512, idx - 138240);
}

// ---------------- layer 1: float conv 3->128 + relu + b1 + bn1 -> bf16 sign ----------------
__global__ __launch_bounds__(128) void conv1_kernel(
    const float* __restrict__ x, const float* __restrict__ w1,
    const float* __restrict__ b1, const float* __restrict__ sc1,
    const float* __restrict__ bi1)
{
    __shared__ float xs[3 * 34 * 3];
    const int tid = threadIdx.x;
    const int y = blockIdx.x, b = blockIdx.y;

    for (int i = tid; i < 3 * 34 * 3; i += 128) xs[i] = 0.f;
    __syncthreads();
    for (int j = 0; j < 3; ++j) {
        int gy = y + j - 1;
        if (gy < 0 || gy >= 32) continue;
        if (tid < 96) {
            int c = tid / 3, ci = tid % 3;
            xs[(j * 34 + c + 1) * 3 + ci] = x[((size_t)(b * 32 + gy) * 32 + c) * 3 + ci];
        }
    }
    __syncthreads();

    float wr[27];
    #pragma unroll
    for (int k = 0; k < 27; ++k) wr[k] = w1[k * 128 + tid];
    const float bv = b1[tid], scv = sc1[tid], biv = bi1[tid];

    for (int c = 0; c < 32; ++c) {
        float sum = 0.f;
        #pragma unroll
        for (int ky = 0; ky < 3; ++ky)
            #pragma unroll
            for (int kx = 0; kx < 3; ++kx)
                #pragma unroll
                for (int ci = 0; ci < 3; ++ci)
                    sum += xs[(ky * 34 + c + kx) * 3 + ci] * wr[(ky * 3 + kx) * 3 + ci];
        float h = fmaxf(sum + bv, 0.f);
        float f = __fadd_rn(__fmul_rn(h, scv), biv);
        g_X2[((size_t)(b * 32 + y) * 32 + c) * 128 + tid] = (f > 0.f) ? 0x3F80 : 0xBF80;
    }
}

// ---------------- layer params ----------------
template <int L> struct LP;
template <> struct LP<2> { static constexpr int H=32,W=32,CIN=128,COUT=128,KSPLIT=1; static constexpr bool POOL=true,  FOUT=false; };
template <> struct LP<3> { static constexpr int H=16,W=16,CIN=128,COUT=256,KSPLIT=1; static constexpr bool POOL=false, FOUT=false; };
template <> struct LP<4> { static constexpr int H=16,W=16,CIN=256,COUT=256,KSPLIT=2; static constexpr bool POOL=true,  FOUT=false; };
template <> struct LP<5> { static constexpr int H=8, W=8, CIN=256,COUT=512,KSPLIT=1; static constexpr bool POOL=false, FOUT=false; };
template <> struct LP<6> { static constexpr int H=8, W=8, CIN=512,COUT=512,KSPLIT=2; static constexpr bool POOL=true,  FOUT=true;  };

// ---------------- binary conv: bf16 HMMA implicit GEMM ----------------
// block 128 thr = 4 n-warps; warp tile m64 x (NFRAG*8); plain unrolled kc loop (R12 style).
// NFRAG=4: CTA N=128 (validated R12 shape).  NFRAG=8: CTA N=256, epilogue in 2 rounds.
template <int L, int NFRAG>
__global__ __launch_bounds__(128) void tcconv(const float* __restrict__ scale,
                                              const float* __restrict__ bias)
{
    constexpr int H = LP<L>::H, W = LP<L>::W, CIN = LP<L>::CIN, COUT = LP<L>::COUT;
    constexpr int KSPLIT = LP<L>::KSPLIT;
    constexpr bool POOL = LP<L>::POOL, FOUT = LP<L>::FOUT;
    constexpr int NB = NFRAG * 32;                  // CTA n-width
    constexpr int ROUNDS = NFRAG / 4;               // epilogue rounds of 128 cols
    constexpr int MROWS = 64 / W;
    constexpr int TPI = H / MROWS;
    constexpr int SROWS = MROWS + 2;
    constexpr int CINS = CIN / KSPLIT;
    constexpr int CPP16 = CINS / 8;                 // 16B units per pixel (per ks chunk)
    constexpr int KC = CINS / 16;                   // k16 chunks per tap per ks
    constexpr int A_BYTES = SROWS * W * CINS * 2;
    constexpr int RES_BYTES = 64 * 132 * 4;
    constexpr int SM_BYTES = (A_BYTES > RES_BYTES ? A_BYTES : RES_BYTES);

    const uint16_t* __restrict__ Xin;
    const uint16_t* __restrict__ BT;
    uint16_t* __restrict__ Xout = nullptr;
    float*    __restrict__ Fout = nullptr;
    if constexpr (L == 2)      { Xin = g_X2; BT = g_B2; Xout = g_X3; }
    else if constexpr (L == 3) { Xin = g_X3; BT = g_B3; Xout = g_X4; }
    else if constexpr (L == 4) { Xin = g_X4; BT = g_B4; Xout = g_X5; }
    else if constexpr (L == 5) { Xin = g_X5; BT = g_B5; Xout = g_X6; }
    else                       { Xin = g_X6; BT = g_B6; Fout = g_H6; }

    __shared__ __align__(16) uint8_t smem[SM_BYTES + 16];
    float* sR = reinterpret_cast<float*>(smem);

    const int tid  = threadIdx.x;
    const int lane = tid & 31, wn = tid >> 5;       // 4 n-warps
    const int group = lane >> 2, tig = lane & 3;
    const int q = lane >> 3, rr = lane & 7;
    const int h = q >> 1;                           // k16-half (16B unit) this lane feeds

    const int bx = blockIdx.x, ny = blockIdx.y;
    const int b = bx / TPI, tile = bx % TPI;
    const int iy0 = tile * MROWS;
    const int nb0 = ny * (NB / 32) + wn * (NFRAG / 4);   // first 32-cout block of warp

    const uint32_t sbase = (uint32_t)__cvta_generic_to_shared(smem);
    const uint32_t zaddr = sbase + SM_BYTES;
    if (tid < 4) *reinterpret_cast<uint32_t*>(smem + SM_BYTES + tid * 4) = 0u;

    // per-lane A pixel per m-frag (4 frags -> m64)
    int ry[4], px[4];
    #pragma unroll
    for (int mi = 0; mi < 4; ++mi) {
        int p = mi * 16 + (q & 1) * 8 + rr;
        ry[mi] = p / W; px[mi] = p - ry[mi] * W;
    }

    float acc[4][NFRAG][4];
    #pragma unroll
    for (int mi = 0; mi < 4; ++mi)
        #pragma unroll
        for (int nf = 0; nf < NFRAG; ++nf)
            #pragma unroll
            for (int v = 0; v < 4; ++v) acc[mi][nf][v] = 0.f;

    for (int ks = 0; ks < KSPLIT; ++ks) {
        if (ks) __syncthreads();
        // ---- stage A rows iy0-1 .. iy0+MROWS of k-chunk ks, pixel-XOR swizzled ----
        {
            constexpr int NV = SROWS * W * CPP16;
            for (int i = tid; i < NV; i += 128) {
                int sp = i / CPP16, c16 = i - sp * CPP16;
                int gy = iy0 - 1 + sp / W, gx = sp % W;
                uint4 v = make_uint4(0, 0, 0, 0);
                if ((unsigned)gy < (unsigned)H)
                    v = *reinterpret_cast<const uint4*>(
                        Xin + (((size_t)b * H + gy) * W + gx) * CIN + ks * CINS + c16 * 8);
                int d16 = sp * CPP16 + (c16 ^ (sp & 7));
                *reinterpret_cast<uint4*>(smem + d16 * 16) = v;
            }
        }
        __syncthreads();

        for (int tap = 0; tap < 9; ++tap) {
            const int ky = tap / 3, kx = tap % 3;
            uint32_t abase[4], ax7[4]; bool av[4];
            #pragma unroll
            for (int mi = 0; mi < 4; ++mi) {
                int sx = px[mi] + kx - 1;
                av[mi] = ((unsigned)sx < (unsigned)W);     // row halo staged as zeros
                int sp = (ry[mi] + ky) * W + sx;
                abase[mi] = sbase + (uint32_t)(sp * CPP16 * 16);
                ax7[mi]   = (uint32_t)(sp & 7);
            }
            // fragment-major B: one 128-uint2 row per (nblk, kcf)
            const uint2* Bw[NFRAG / 4];
            #pragma unroll
            for (int g = 0; g < NFRAG / 4; ++g)
                Bw[g] = reinterpret_cast<const uint2*>(BT)
                    + (((size_t)tap * (COUT / 32) + nb0 + g) * (CIN / 16) + ks * KC) * 128 + lane;
            #pragma unroll 2
            for (int kc = 0; kc < KC; ++kc) {
                uint32_t A[4][4];
                #pragma unroll
                for (int mi = 0; mi < 4; ++mi) {
                    uint32_t u = ((uint32_t)(kc * 2 + h)) ^ ax7[mi];
                    uint32_t ad = av[mi] ? (abase[mi] + (u << 4)) : zaddr;
                    asm volatile(
                        "ldmatrix.sync.aligned.m8n8.x4.shared.b16 {%0,%1,%2,%3}, [%4];"
                        : "=r"(A[mi][0]), "=r"(A[mi][1]), "=r"(A[mi][2]), "=r"(A[mi][3])
                        : "r"(ad));
                }
                #pragma unroll
                for (int nf = 0; nf < NFRAG; ++nf) {
                    uint2 bw = Bw[nf >> 2][(kc * 4 + (nf & 3)) * 32];
                    #pragma unroll
                    for (int mi = 0; mi < 4; ++mi) {
                        asm volatile(
                            "mma.sync.aligned.m16n8k16.row.col.f32.bf16.bf16.f32 "
                            "{%0,%1,%2,%3}, {%4,%5,%6,%7}, {%8,%9}, {%0,%1,%2,%3};"
                            : "+f"(acc[mi][nf][0]), "+f"(acc[mi][nf][1]),
                              "+f"(acc[mi][nf][2]), "+f"(acc[mi][nf][3])
                            : "r"(A[mi][0]), "r"(A[mi][1]), "r"(A[mi][2]), "r"(A[mi][3]),
                              "r"(bw.x), "r"(bw.y));
                    }
                }
            }
        }
    }
    __syncthreads();   // A no longer needed; reuse smem for results

    // ---- epilogue in ROUNDS rounds of 64 px x 128 cols ----
    #pragma unroll
    for (int rd = 0; rd < ROUNDS; ++rd) {
        const bool mine = (ROUNDS == 1) || ((wn >> 1) == rd);
        if (mine) {
            const int cb = (ROUNDS == 1) ? wn * 32 : (wn & 1) * 64;
            #pragma unroll
            for (int mi = 0; mi < 4; ++mi) {
                int r0 = mi * 16 + group;
                #pragma unroll
                for (int nf = 0; nf < NFRAG; ++nf) {
                    int col = cb + nf * 8 + tig * 2;
                    *reinterpret_cast<float2*>(&sR[r0 * 132 + col]) =
                        make_float2(acc[mi][nf][0], acc[mi][nf][1]);
                    *reinterpret_cast<float2*>(&sR[(r0 + 8) * 132 + col]) =
                        make_float2(acc[mi][nf][2], acc[mi][nf][3]);
                }
            }
        }
        __syncthreads();

        const int nyb = ny * NB + rd * 128;
        if constexpr (POOL) {
            // 16 out px x 128 n; 8 threads per px, 16 n each
            int po = tid >> 3;
            int n0 = (tid & 7) * 16;
            int yo_l = po / (W / 2), xo_l = po % (W / 2);
            int p00 = (2 * yo_l) * W + 2 * xo_l;
            float fv[16];
            #pragma unroll
            for (int j = 0; j < 16; ++j) {
                int n = n0 + j;
                float m = fmaxf(fmaxf(sR[p00 * 132 + n],       sR[(p00 + 1) * 132 + n]),
                                fmaxf(sR[(p00 + W) * 132 + n], sR[(p00 + W + 1) * 132 + n]));
                m = fmaxf(m, 0.f);
                int ng = nyb + n;
                fv[j] = __fadd_rn(__fmul_rn(m, scale[ng]), bias[ng]);
            }
            int yo = iy0 / 2 + yo_l;
            size_t obase = (((size_t)b * (H / 2) + yo) * (W / 2) + xo_l) * COUT + nyb + n0;
            if constexpr (FOUT) {
                #pragma unroll
                for (int qq = 0; qq < 4; ++qq)
                    *reinterpret_cast<float4*>(Fout + obase + qq * 4) =
                        make_float4(fv[4*qq], fv[4*qq+1], fv[4*qq+2], fv[4*qq+3]);
            } else {
                uint32_t wds[8];
                #pragma unroll
                for (int qq = 0; qq < 8; ++qq)
                    wds[qq] = ((fv[2*qq]   > 0.f) ? 0x3F80u : 0xBF80u) |
                             (((fv[2*qq+1] > 0.f) ? 0x3F80u : 0xBF80u) << 16);
                uint4* op = reinterpret_cast<uint4*>(Xout + obase);
                op[0] = make_uint4(wds[0], wds[1], wds[2], wds[3]);
                op[1] = make_uint4(wds[4], wds[5], wds[6], wds[7]);
            }
        } else {
            // 64 px x 128 n; 8 iterations of 128 thr x 8 n
            #pragma unroll
            for (int it = 0; it < 8; ++it) {
                int t = it * 128 + tid;
                int lp = t >> 4;
                int n0 = (t & 15) * 8;
                int y = iy0 + lp / W, x = lp % W;
                float fv[8];
                #pragma unroll
                for (int j = 0; j < 8; ++j) {
                    int n = n0 + j;
                    float v = fmaxf(sR[lp * 132 + n], 0.f);
                    int ng = nyb + n;
                    fv[j] = __fadd_rn(__fmul_rn(v, scale[ng]), bias[ng]);
                }
                uint32_t wds[4];
                #pragma unroll
                for (int qq = 0; qq < 4; ++qq)
                    wds[qq] = ((fv[2*qq]   > 0.f) ? 0x3F80u : 0xBF80u) |
                             (((fv[2*qq+1] > 0.f) ? 0x3F80u : 0xBF80u) << 16);
                size_t obase = (((size_t)b * H + y) * W + x) * COUT + nyb + n0;
                *reinterpret_cast<uint4*>(Xout + obase) = make_uint4(wds[0], wds[1], wds[2], wds[3]);
            }
        }
        if (rd + 1 < ROUNDS) __syncthreads();
    }
}

// ---------------- dense (512->10) + softmax, one warp per pixel ----------------
__global__ __launch_bounds__(128) void dense_kernel(
    const float* __restrict__ dw, const float* __restrict__ db, float* __restrict__ out)
{
    __shared__ float sdw[512 * 10];
    const int tid = threadIdx.x;
    for (int i = tid; i < 5120; i += 128) {
        int c = i / 10, d = i % 10;
        sdw[d * 512 + c] = dw[i];
    }
    __syncthreads();
    const int warp = tid >> 5, lane = tid & 31;
    const int p = blockIdx.x * 4 + warp;
    float lg[10];
    #pragma unroll
    for (int d = 0; d < 10; ++d) lg[d] = 0.f;
    for (int c = lane; c < 512; c += 32) {
        float hh = g_H6[(size_t)p * 512 + c];
        #pragma unroll
        for (int d = 0; d < 10; ++d) lg[d] += hh * sdw[d * 512 + c];
    }
    #pragma unroll
    for (int d = 0; d < 10; ++d)
        for (int off = 16; off; off >>= 1)
            lg[d] += __shfl_xor_sync(FULLMASK, lg[d], off);
    if (lane == 0) {
        float l[10], mx = -1e30f;
        #pragma unroll
        for (int d = 0; d < 10; ++d) { l[d] = lg[d] + db[d]; mx = fmaxf(mx, l[d]); }
        float e[10], ssum = 0.f;
        #pragma unroll
        for (int d = 0; d < 10; ++d) { e[d] = expf(l[d] - mx); ssum += e[d]; }
        float inv = 1.f / ssum;
        #pragma unroll
        for (int d = 0; d < 10; ++d) out[(size_t)p * 10 + d] = e[d] * inv;
    }
}

// ---------------- launch ----------------
extern "C" void kernel_launch(void* const* d_in, const int* in_sizes, int n_in,
                              void* d_out, int out_size)
{
    const float* P[22];
    for (int i = 0; i < 22 && i < n_in; ++i) P[i] = (const float*)d_in[i];

    const float *x, *w1, *b1, *w2, *w3, *w4, *w5, *w6;
    const float *bn1s, *bn1b, *bn2s, *bn2b, *bn3s, *bn3b, *bn4s, *bn4b, *bn5s, *bn5b, *bn6s, *bn6b;
    const float *dw, *db;

    if (in_sizes[3] == 147456) {
        // setup_inputs dict order
        x = P[0];  w1 = P[1]; b1 = P[2];
        w2 = P[3]; w3 = P[4]; w4 = P[5]; w5 = P[6]; w6 = P[7];
        bn1s = P[8];  bn1b = P[9];  bn2s = P[10]; bn2b = P[11];
        bn3s = P[12]; bn3b = P[13]; bn4s = P[14]; bn4b = P[15];
        bn5s = P[16]; bn5b = P[17]; bn6s = P[18]; bn6b = P[19];
        dw = P[20]; db = P[21];
    } else {
        // reference() signature order
        x = P[0];  w1 = P[1]; b1 = P[2]; bn1s = P[3]; bn1b = P[4];
        w2 = P[5];  bn2s = P[6];  bn2b = P[7];
        w3 = P[8];  bn3s = P[9];  bn3b = P[10];
        w4 = P[11]; bn4s = P[12]; bn4b = P[13];
        w5 = P[14]; bn5s = P[15]; bn5b = P[16];
        w6 = P[17]; bn6s = P[18]; bn6b = P[19];
        dw = P[20]; db = P[21];
    }

    pack_all<<<(285696 + 255) / 256, 256>>>(w2, w3, w4, w5, w6);

    conv1_kernel<<<dim3(32, 128), 128>>>(x, w1, b1, bn1s, bn1b);

    tcconv<2, 4><<<dim3(128 * 16, 1), 128>>>(bn2s, bn2b);   // COUT=128: validated R12 shape
    tcconv<3, 8><<<dim3(128 * 4, 1),  128>>>(bn3s, bn3b);   // CTA N=256
    tcconv<4, 8><<<dim3(128 * 4, 1),  128>>>(bn4s, bn4b);
    tcconv<5, 8><<<dim3(128, 2),      128>>>(bn5s, bn5b);
    tcconv<6, 8><<<dim3(128, 2),      128>>>(bn6s, bn6b);

    dense_kernel<<<512, 128>>>(dw, db, (float*)d_out);
}